// round 1
// baseline (speedup 1.0000x reference)
#include <cuda_runtime.h>
#include <cuda_bf16.h>

#define N_NODES 100000
#define N_EDGES 1600000
#define C 64
#define TILE 64
#define HPAD 68   // padded row stride (floats) for h/hn tiles

// ---------------- scratch (device globals: no allocations allowed) ----------------
__device__ __align__(16) float g_h0[N_NODES * C];
__device__ __align__(16) float g_h1[N_NODES * C];
__device__ __align__(16) float g_agg[N_NODES * C];
__device__ __align__(16) float g_ideg[N_NODES];

// ---------------- utility kernels ----------------
__global__ void zero_kernel(float4* __restrict__ p, int n4) {
    int i = blockIdx.x * blockDim.x + threadIdx.x;
    if (i < n4) p[i] = make_float4(0.f, 0.f, 0.f, 0.f);
}

__global__ void deg_kernel(const int* __restrict__ dst, float* __restrict__ deg) {
    int e = blockIdx.x * blockDim.x + threadIdx.x;
    if (e < N_EDGES) atomicAdd(&deg[dst[e]], 1.0f);
}

__global__ void invdeg_kernel(float* __restrict__ deg) {
    int i = blockIdx.x * blockDim.x + threadIdx.x;
    if (i < N_NODES) deg[i] = 1.0f / fmaxf(deg[i], 1.0f);
}

// ---------------- edge scatter: agg[dst] += h[src] (vec4 reductions) ----------------
// work item = (edge, 16B chunk). 16 consecutive threads cover one edge's 64 floats.
__global__ void scatter_kernel(const float* __restrict__ h,
                               const int* __restrict__ src,
                               const int* __restrict__ dst,
                               float* __restrict__ agg) {
    int t = blockIdx.x * blockDim.x + threadIdx.x;
    int e = t >> 4;
    if (e >= N_EDGES) return;
    int c4 = (t & 15) << 2;
    int s = __ldg(&src[e]);
    int d = __ldg(&dst[e]);
    float4 v = *(const float4*)(h + s * C + c4);
    float* a = agg + d * C + c4;
    asm volatile("red.global.add.v4.f32 [%0], {%1, %2, %3, %4};"
                 :: "l"(a), "f"(v.x), "f"(v.y), "f"(v.z), "f"(v.w)
                 : "memory");
}

// ---------------- fused: out = rownorm(h@W1^T + (agg*invdeg)@W2^T + b) [-> BN -> ReLU] ----
// Block: 256 threads, tile of 64 nodes x 64 channels. Thread owns 4 nodes x 4 channels.
// W stored TRANSPOSED in smem (sw[k][c]) -> per-k float4 W loads are 256B contiguous
// across the warp (conflict-free); h/hn scalar loads are 2-address broadcasts.
__global__ __launch_bounds__(256) void sage_fused_kernel(
    const float* __restrict__ h, const float* __restrict__ agg,
    const float* __restrict__ ideg,
    const float* __restrict__ w1, const float* __restrict__ w2,
    const float* __restrict__ b2,
    const float* __restrict__ bn_g, const float* __restrict__ bn_b,
    const float* __restrict__ bn_m, const float* __restrict__ bn_v,
    float* __restrict__ out, int apply_bn)
{
    extern __shared__ float smem[];
    float* sh  = smem;                    // [64][HPAD]
    float* sn  = sh + TILE * HPAD;        // [64][HPAD]
    float* sw1 = sn + TILE * HPAD;        // [64][64] transposed: sw1[k*64+c]
    float* sw2 = sw1 + 64 * 64;           // [64][64]
    float* sb  = sw2 + 64 * 64;           // [64]
    float* ssc = sb + 64;                 // [64] bn scale
    float* sbs = ssc + 64;                // [64] bn bias

    const int t = threadIdx.x;
    const int node0 = blockIdx.x * TILE;

    // load weights transposed (w global layout [c][k])
    #pragma unroll
    for (int i = t; i < 64 * 64; i += 256) {
        int c = i >> 6, k = i & 63;
        sw1[k * 64 + c] = w1[i];
        sw2[k * 64 + c] = w2[i];
    }
    if (t < 64) {
        sb[t] = b2[t];
        if (apply_bn) {
            float sc = bn_g[t] * rsqrtf(bn_v[t] + 1e-5f);
            ssc[t] = sc;
            sbs[t] = bn_b[t] - bn_m[t] * sc;
        }
    }

    // load h / hn tiles (coalesced: 16 threads cover one row). mean fused here.
    #pragma unroll
    for (int r = 0; r < 4; r++) {
        int j = t + 256 * r;
        int row = j >> 4;
        int c4 = (j & 15) << 2;
        int node = node0 + row;
        float4 hv = make_float4(0.f, 0.f, 0.f, 0.f);
        float4 av = make_float4(0.f, 0.f, 0.f, 0.f);
        float id = 0.f;
        if (node < N_NODES) {
            hv = *(const float4*)(h + node * C + c4);
            av = *(const float4*)(agg + node * C + c4);
            id = ideg[node];
        }
        *(float4*)(sh + row * HPAD + c4) = hv;
        av.x *= id; av.y *= id; av.z *= id; av.w *= id;
        *(float4*)(sn + row * HPAD + c4) = av;
    }
    __syncthreads();

    const int cg = (t & 15) << 2;   // channel base
    const int ng = (t >> 4) << 2;   // node base within tile

    float acc[4][4];
    #pragma unroll
    for (int i = 0; i < 4; i++)
        #pragma unroll
        for (int j = 0; j < 4; j++) acc[i][j] = 0.f;

    #pragma unroll 8
    for (int k = 0; k < 64; k++) {
        float4 w1v = *(const float4*)(sw1 + k * 64 + cg);
        float4 w2v = *(const float4*)(sw2 + k * 64 + cg);
        #pragma unroll
        for (int i = 0; i < 4; i++) {
            float a = sh[(ng + i) * HPAD + k];
            float b = sn[(ng + i) * HPAD + k];
            acc[i][0] = fmaf(a, w1v.x, fmaf(b, w2v.x, acc[i][0]));
            acc[i][1] = fmaf(a, w1v.y, fmaf(b, w2v.y, acc[i][1]));
            acc[i][2] = fmaf(a, w1v.z, fmaf(b, w2v.z, acc[i][2]));
            acc[i][3] = fmaf(a, w1v.w, fmaf(b, w2v.w, acc[i][3]));
        }
    }

    // epilogue: +bias, row L2-norm (reduce across 16 threads sharing node group),
    // optional BN+ReLU, vectorized store.
    float ss[4];
    #pragma unroll
    for (int i = 0; i < 4; i++) {
        float s = 0.f;
        #pragma unroll
        for (int j = 0; j < 4; j++) {
            float v = acc[i][j] + sb[cg + j];
            acc[i][j] = v;
            s = fmaf(v, v, s);
        }
        ss[i] = s;
    }
    #pragma unroll
    for (int m = 1; m < 16; m <<= 1)
        #pragma unroll
        for (int i = 0; i < 4; i++)
            ss[i] += __shfl_xor_sync(0xffffffffu, ss[i], m);

    #pragma unroll
    for (int i = 0; i < 4; i++) {
        int node = node0 + ng + i;
        if (node >= N_NODES) continue;
        float nrm = sqrtf(ss[i]);
        float scale = 1.0f / fmaxf(nrm, 1e-12f);
        float4 o;
        float v0 = acc[i][0] * scale;
        float v1 = acc[i][1] * scale;
        float v2 = acc[i][2] * scale;
        float v3 = acc[i][3] * scale;
        if (apply_bn) {
            v0 = fmaxf(fmaf(v0, ssc[cg + 0], sbs[cg + 0]), 0.f);
            v1 = fmaxf(fmaf(v1, ssc[cg + 1], sbs[cg + 1]), 0.f);
            v2 = fmaxf(fmaf(v2, ssc[cg + 2], sbs[cg + 2]), 0.f);
            v3 = fmaxf(fmaf(v3, ssc[cg + 3], sbs[cg + 3]), 0.f);
        }
        o.x = v0; o.y = v1; o.z = v2; o.w = v3;
        *(float4*)(out + node * C + cg) = o;
    }
}

// ---------------- host ----------------
static const int SMEM_BYTES = (2 * TILE * HPAD + 2 * 64 * 64 + 3 * 64) * 4;

extern "C" void kernel_launch(void* const* d_in, const int* in_sizes, int n_in,
                              void* d_out, int out_size) {
    const float* x    = (const float*)d_in[0];
    const int*   esrc = (const int*)d_in[1];
    const int*   edst = (const int*)d_in[2];

    // Input-order sniffing: dict order has w1_1 (4096) at index 6,
    // signature order has bn_g_0 (64) there.
    int iw1[3], iw2[3], ib2[3], ibn[2][4];
    if (n_in > 6 && in_sizes[6] == 4096) {
        // dict order: w1_0,w2_0,b2_0, w1_1,w2_1,b2_1, w1_2,w2_2,b2_2, bn0{g,b,m,v}, bn1{g,b,m,v}
        for (int l = 0; l < 3; l++) { iw1[l] = 3 + 3 * l; iw2[l] = 4 + 3 * l; ib2[l] = 5 + 3 * l; }
        for (int l = 0; l < 2; l++)
            for (int j = 0; j < 4; j++) ibn[l][j] = 12 + 4 * l + j;
    } else {
        // signature order: w1_0,w2_0,b2_0,bn0{g,b,m,v}, w1_1,w2_1,b2_1,bn1{g,b,m,v}, w1_2,w2_2,b2_2
        iw1[0] = 3;  iw2[0] = 4;  ib2[0] = 5;
        for (int j = 0; j < 4; j++) ibn[0][j] = 6 + j;
        iw1[1] = 10; iw2[1] = 11; ib2[1] = 12;
        for (int j = 0; j < 4; j++) ibn[1][j] = 13 + j;
        iw1[2] = 17; iw2[2] = 18; ib2[2] = 19;
    }

    float *h0, *h1, *agg, *ideg;
    cudaGetSymbolAddress((void**)&h0,  g_h0);
    cudaGetSymbolAddress((void**)&h1,  g_h1);
    cudaGetSymbolAddress((void**)&agg, g_agg);
    cudaGetSymbolAddress((void**)&ideg, g_ideg);

    cudaFuncSetAttribute(sage_fused_kernel,
                         cudaFuncAttributeMaxDynamicSharedMemorySize, SMEM_BYTES);

    const int NB_FEAT4 = (N_NODES * C / 4 + 255) / 256;      // zero agg
    const int NB_DEG4  = (N_NODES / 4 + 255) / 256;          // zero deg
    const int NB_EDGE  = (N_EDGES + 255) / 256;
    const int NB_SCAT  = (N_EDGES * 16 + 255) / 256;
    const int NB_NODE  = (N_NODES + 255) / 256;
    const int NB_GEMM  = (N_NODES + TILE - 1) / TILE;

    // degree (edge_dst only) -> inverse, computed once, reused all layers
    zero_kernel<<<NB_DEG4, 256>>>((float4*)ideg, N_NODES / 4);
    deg_kernel<<<NB_EDGE, 256>>>(edst, ideg);
    invdeg_kernel<<<NB_NODE, 256>>>(ideg);

    const float* hin = x;
    float* houts[3] = {h0, h1, (float*)d_out};

    for (int l = 0; l < 3; l++) {
        zero_kernel<<<NB_FEAT4, 256>>>((float4*)agg, N_NODES * C / 4);
        scatter_kernel<<<NB_SCAT, 256>>>(hin, esrc, edst, agg);
        int has_bn = (l < 2);
        sage_fused_kernel<<<NB_GEMM, 256, SMEM_BYTES>>>(
            hin, agg, ideg,
            (const float*)d_in[iw1[l]], (const float*)d_in[iw2[l]],
            (const float*)d_in[ib2[l]],
            has_bn ? (const float*)d_in[ibn[l][0]] : (const float*)d_in[ib2[l]],
            has_bn ? (const float*)d_in[ibn[l][1]] : (const float*)d_in[ib2[l]],
            has_bn ? (const float*)d_in[ibn[l][2]] : (const float*)d_in[ib2[l]],
            has_bn ? (const float*)d_in[ibn[l][3]] : (const float*)d_in[ib2[l]],
            houts[l], has_bn);
        hin = houts[l];
    }
}